// round 2
// baseline (speedup 1.0000x reference)
#include <cuda_runtime.h>

#define NBLK 128
#define NTHR 256
#define Bz   32
#define Ssz  2048
#define Isz  128
#define Hsz  512
#define Osz  128
#define K0   640
#define K1   1024
#define PITCH 1036

// smem layout (float offsets)
#define OFF_WZR0 0
#define OFF_WG0  5120
#define OFF_WZR1 7680
#define OFF_WG1  15872
#define OFF_WY   19968
#define OFF_BIAS 20480
#define OFF_PART 20512
#define OFF_STAGE 21664
#define SMEM_FLOATS 54816
#define SMEM_BYTES (SMEM_FLOATS * 4)

// ---------------- global scratch ----------------
__device__ float g_h0[2][Bz * Hsz];
__device__ float g_h1[2][Bz * Hsz];
__device__ float g_z0[Bz * Hsz];
__device__ float g_r0[Bz * Hsz];
__device__ float g_z1[Bz * Hsz];
__device__ float g_r1[Bz * Hsz];
__device__ unsigned g_cnt;
__device__ volatile unsigned g_gen;

// ---------------- helpers ----------------
__device__ __forceinline__ float4 ldcg4(const float* p) {
    float4 v;
    asm volatile("ld.global.cg.v4.f32 {%0,%1,%2,%3}, [%4];"
                 : "=f"(v.x), "=f"(v.y), "=f"(v.z), "=f"(v.w) : "l"(p));
    return v;
}
__device__ __forceinline__ float ldcgf(const float* p) {
    float v;
    asm volatile("ld.global.cg.f32 %0, [%1];" : "=f"(v) : "l"(p));
    return v;
}
__device__ __forceinline__ void stcgf(float* p, float v) {
    asm volatile("st.global.cg.f32 [%0], %1;" :: "l"(p), "f"(v));
}

__device__ __forceinline__ void grid_sync() {
    __threadfence();          // drain stores + flush L1D (gpu-scope fence)
    __syncthreads();
    if (threadIdx.x == 0) {
        unsigned gen = g_gen;
        if (atomicAdd(&g_cnt, 1u) == (unsigned)(NBLK - 1)) {
            g_cnt = 0u;
            __threadfence();
            g_gen = gen + 1u;
        } else {
            while (g_gen == gen) { }
        }
        __threadfence();
    }
    __syncthreads();
}

__device__ __forceinline__ float sigmoid_(float x) {
    return 1.0f / (1.0f + __expf(-x));
}
__device__ __forceinline__ float tanh_(float x) {
    return 1.0f - 2.0f / (__expf(2.0f * x) + 1.0f);
}

// Dot phase: NROW rows (4 or 8) x 32 batches, K split KSPLIT ways among warps.
// warp w: rowgroup rg = w/KSPLIT (4 rows), K-chunk kq = w%KSPLIT.
// lane = batch. Each lane accumulates 4 rows over its K-chunk; partials to smem.
template <int K, int NROW, int KSPLIT>
__device__ __forceinline__ void dot_partials(const float* __restrict__ Wsm,
                                             const float* __restrict__ stg,
                                             float* __restrict__ part) {
    const int w = threadIdx.x >> 5, lane = threadIdx.x & 31;
    const int rg = w / KSPLIT, kq = w % KSPLIT;
    const int klen = K / KSPLIT;
    const float* wbase = Wsm + (rg * 4) * K + kq * klen;
    const float* sbase = stg + lane * PITCH + kq * klen;
    float a0 = 0.f, a1 = 0.f, a2 = 0.f, a3 = 0.f;
#pragma unroll 4
    for (int k = 0; k < klen; k += 4) {
        float4 sv = *(const float4*)(sbase + k);
        float4 w0 = *(const float4*)(wbase + k);
        float4 w1 = *(const float4*)(wbase + K + k);
        float4 w2 = *(const float4*)(wbase + 2 * K + k);
        float4 w3 = *(const float4*)(wbase + 3 * K + k);
        a0 = fmaf(w0.x, sv.x, fmaf(w0.y, sv.y, fmaf(w0.z, sv.z, fmaf(w0.w, sv.w, a0))));
        a1 = fmaf(w1.x, sv.x, fmaf(w1.y, sv.y, fmaf(w1.z, sv.z, fmaf(w1.w, sv.w, a1))));
        a2 = fmaf(w2.x, sv.x, fmaf(w2.y, sv.y, fmaf(w2.z, sv.z, fmaf(w2.w, sv.w, a2))));
        a3 = fmaf(w3.x, sv.x, fmaf(w3.y, sv.y, fmaf(w3.z, sv.z, fmaf(w3.w, sv.w, a3))));
    }
    part[(w * 4 + 0) * 32 + lane] = a0;
    part[(w * 4 + 1) * 32 + lane] = a1;
    part[(w * 4 + 2) * 32 + lane] = a2;
    part[(w * 4 + 3) * 32 + lane] = a3;
}

extern "C" __global__ void __launch_bounds__(NTHR, 1)
gru_persistent(const float* __restrict__ input, const float* __restrict__ h0in,
               const float* __restrict__ Wx0, const float* __restrict__ Wh0,
               const float* __restrict__ bh0, const float* __restrict__ Wx1,
               const float* __restrict__ Wh1, const float* __restrict__ bh1,
               const float* __restrict__ Why, const float* __restrict__ bhy,
               float* __restrict__ out) {
    extern __shared__ float sm[];
    const int p = blockIdx.x, tid = threadIdx.x;

    // ---- load weight slices into smem (once per launch) ----
    for (int i = tid; i < 8 * K0; i += NTHR) {
        int r = i / K0, k = i - r * K0;
        int row = 8 * p + r;  // packed z,r rows 0..1023
        sm[OFF_WZR0 + i] = (k < Isz) ? Wx0[row * Isz + k] : Wh0[row * Hsz + k - Isz];
    }
    for (int i = tid; i < 4 * K0; i += NTHR) {
        int r = i / K0, k = i - r * K0;
        int row = 2 * Hsz + 4 * p + r;  // g rows 1024..1535
        sm[OFF_WG0 + i] = (k < Isz) ? Wx0[row * Isz + k] : Wh0[row * Hsz + k - Isz];
    }
    for (int i = tid; i < 8 * K1; i += NTHR) {
        int r = i >> 10, k = i & 1023;
        int row = 8 * p + r;
        sm[OFF_WZR1 + i] = (k < Hsz) ? Wx1[row * Hsz + k] : Wh1[row * Hsz + k - Hsz];
    }
    for (int i = tid; i < 4 * K1; i += NTHR) {
        int r = i >> 10, k = i & 1023;
        int row = 2 * Hsz + 4 * p + r;
        sm[OFF_WG1 + i] = (k < Hsz) ? Wx1[row * Hsz + k] : Wh1[row * Hsz + k - Hsz];
    }
    for (int i = tid; i < Hsz; i += NTHR) sm[OFF_WY + i] = Why[p * Hsz + i];
    if (tid < 8)       sm[OFF_BIAS + tid] = bh0[8 * p + tid];
    else if (tid < 12) sm[OFF_BIAS + tid] = bh0[2 * Hsz + 4 * p + tid - 8];
    else if (tid < 20) sm[OFF_BIAS + tid] = bh1[8 * p + tid - 12];
    else if (tid < 24) sm[OFF_BIAS + tid] = bh1[2 * Hsz + 4 * p + tid - 20];
    else if (tid == 24) sm[OFF_BIAS + tid] = bhy[p];

    // ---- init hidden state (buffer 0) : 32768 elements, one per thread ----
    {
        int i = p * NTHR + tid;
        int b = i >> 10, rest = i & 1023;
        float v = h0in[i];
        if (rest < Hsz) stcgf(&g_h0[0][b * Hsz + rest], v);
        else            stcgf(&g_h1[0][b * Hsz + rest - Hsz], v);
    }
    __syncthreads();
    grid_sync();

    float* stg = sm + OFF_STAGE;
    float* part = sm + OFF_PART;

    for (int t = 0; t < Ssz; ++t) {
        const int ob = t & 1, nb = ob ^ 1;

        // ===== Phase A: stage [x_t | h0_old]; compute zr0 (8 rows) =====
        for (int i = tid; i < Bz * (Isz / 4); i += NTHR) {
            int b = i >> 5, k = (i & 31) << 2;
            *(float4*)(stg + b * PITCH + k) =
                *(const float4*)(input + (b * Ssz + t) * Isz + k);
        }
        for (int i = tid; i < Bz * (Hsz / 4); i += NTHR) {
            int b = i >> 7, k = (i & 127) << 2;
            *(float4*)(stg + b * PITCH + Isz + k) = ldcg4(&g_h0[ob][b * Hsz + k]);
        }
        __syncthreads();
        dot_partials<K0, 8, 4>(sm + OFF_WZR0, stg, part);
        __syncthreads();
        {
            int rr = tid >> 5, b = tid & 31;
            int rg = rr >> 2, r4 = rr & 3;
            float acc = sm[OFF_BIAS + rr];
#pragma unroll
            for (int kq = 0; kq < 4; ++kq) acc += part[((rg * 4 + kq) * 4 + r4) * 32 + b];
            float s = sigmoid_(acc);
            int j = 8 * p + rr;
            if (j < Hsz) stcgf(&g_z0[b * Hsz + j], s);
            else         stcgf(&g_r0[b * Hsz + j - Hsz], s);
        }
        grid_sync();

        // ===== Phase B: restage h-part = r0*h0_old; compute g0, h0' (4 rows) =====
        for (int i = tid; i < Bz * (Hsz / 4); i += NTHR) {
            int b = i >> 7, k = (i & 127) << 2;
            float4 r = ldcg4(&g_r0[b * Hsz + k]);
            float4 h = ldcg4(&g_h0[ob][b * Hsz + k]);
            *(float4*)(stg + b * PITCH + Isz + k) =
                make_float4(r.x * h.x, r.y * h.y, r.z * h.z, r.w * h.w);
        }
        __syncthreads();
        dot_partials<K0, 4, 8>(sm + OFF_WG0, stg, part);
        __syncthreads();
        if (tid < 128) {
            int r4 = tid >> 5, b = tid & 31;
            float acc = sm[OFF_BIAS + 8 + r4];
#pragma unroll
            for (int w = 0; w < 8; ++w) acc += part[(w * 4 + r4) * 32 + b];
            float g = tanh_(acc);
            int u = 4 * p + r4;
            float z = ldcgf(&g_z0[b * Hsz + u]);
            float h = ldcgf(&g_h0[ob][b * Hsz + u]);
            stcgf(&g_h0[nb][b * Hsz + u], z * h + (1.f - z) * g);
        }
        grid_sync();

        // ===== Phase C: stage [h0' | h1_old]; compute zr1 (8 rows) + y[t-1] =====
        for (int i = tid; i < Bz * (Hsz / 4); i += NTHR) {
            int b = i >> 7, k = (i & 127) << 2;
            *(float4*)(stg + b * PITCH + k) = ldcg4(&g_h0[nb][b * Hsz + k]);
            *(float4*)(stg + b * PITCH + Hsz + k) = ldcg4(&g_h1[ob][b * Hsz + k]);
        }
        __syncthreads();
        dot_partials<K1, 8, 4>(sm + OFF_WZR1, stg, part);
        {
            int w = tid >> 5, lane = tid & 31;
            if (w == 2 || w == 3) {  // K-chunks covering h1 region [512,1024), once each
                const float* sb = stg + lane * PITCH + w * 256;
                const float* wb = sm + OFF_WY + w * 256 - Hsz;
                float a0 = 0.f, a1 = 0.f, a2 = 0.f, a3 = 0.f;
#pragma unroll 4
                for (int k = 0; k < 256; k += 4) {
                    float4 sv = *(const float4*)(sb + k);
                    float4 wv = *(const float4*)(wb + k);
                    a0 = fmaf(wv.x, sv.x, a0); a1 = fmaf(wv.y, sv.y, a1);
                    a2 = fmaf(wv.z, sv.z, a2); a3 = fmaf(wv.w, sv.w, a3);
                }
                part[1024 + (w - 2) * 32 + lane] = (a0 + a1) + (a2 + a3);
            }
        }
        __syncthreads();
        {
            int rr = tid >> 5, b = tid & 31;
            int rg = rr >> 2, r4 = rr & 3;
            float acc = sm[OFF_BIAS + 12 + rr];
#pragma unroll
            for (int kq = 0; kq < 4; ++kq) acc += part[((rg * 4 + kq) * 4 + r4) * 32 + b];
            float s = sigmoid_(acc);
            int j = 8 * p + rr;
            if (j < Hsz) stcgf(&g_z1[b * Hsz + j], s);
            else         stcgf(&g_r1[b * Hsz + j - Hsz], s);
            if (tid < 32 && t > 0) {
                float y = sm[OFF_BIAS + 24];
                y += part[1024 + b] + part[1024 + 32 + b];
                out[(b * Ssz + (t - 1)) * Osz + p] = y;
            }
        }
        grid_sync();

        // ===== Phase D: restage [., r1*h1_old]; compute g1, h1' (4 rows) =====
        for (int i = tid; i < Bz * (Hsz / 4); i += NTHR) {
            int b = i >> 7, k = (i & 127) << 2;
            float4 r = ldcg4(&g_r1[b * Hsz + k]);
            float4 h = ldcg4(&g_h1[ob][b * Hsz + k]);
            *(float4*)(stg + b * PITCH + Hsz + k) =
                make_float4(r.x * h.x, r.y * h.y, r.z * h.z, r.w * h.w);
        }
        __syncthreads();
        dot_partials<K1, 4, 8>(sm + OFF_WG1, stg, part);
        __syncthreads();
        if (tid < 128) {
            int r4 = tid >> 5, b = tid & 31;
            float acc = sm[OFF_BIAS + 20 + r4];
#pragma unroll
            for (int w = 0; w < 8; ++w) acc += part[(w * 4 + r4) * 32 + b];
            float g = tanh_(acc);
            int u = 4 * p + r4;
            float z = ldcgf(&g_z1[b * Hsz + u]);
            float h = ldcgf(&g_h1[ob][b * Hsz + u]);
            stcgf(&g_h1[nb][b * Hsz + u], z * h + (1.f - z) * g);
        }
        grid_sync();
    }

    // ===== Epilogue: y[S-1] + hidden_state (final buffers are index 0) =====
    {
        int b = tid >> 3, sub = tid & 7;  // 32 batches x 8 threads
        const float* wy = sm + OFF_WY + sub * 64;
        const float* h1f = &g_h1[0][b * Hsz + sub * 64];
        float a = 0.f;
#pragma unroll 8
        for (int k = 0; k < 64; k += 4) {
            float4 hv = ldcg4(h1f + k);
            float4 wv = *(const float4*)(wy + k);
            a = fmaf(wv.x, hv.x, fmaf(wv.y, hv.y, fmaf(wv.z, hv.z, fmaf(wv.w, hv.w, a))));
        }
        a += __shfl_down_sync(0xffffffffu, a, 4, 8);
        a += __shfl_down_sync(0xffffffffu, a, 2, 8);
        a += __shfl_down_sync(0xffffffffu, a, 1, 8);
        if (sub == 0) out[(b * Ssz + (Ssz - 1)) * Osz + p] = a + sm[OFF_BIAS + 24];
    }
    {
        int i = p * NTHR + tid;  // 32768 = Bz*2*Hsz
        int b = i >> 10, rest = i & 1023;
        float v = (rest < Hsz) ? ldcgf(&g_h0[0][b * Hsz + rest])
                               : ldcgf(&g_h1[0][b * Hsz + rest - Hsz]);
        out[Bz * Ssz * Osz + i] = v;
    }
}

extern "C" void kernel_launch(void* const* d_in, const int* in_sizes, int n_in,
                              void* d_out, int out_size) {
    cudaFuncSetAttribute(gru_persistent,
                         cudaFuncAttributeMaxDynamicSharedMemorySize, SMEM_BYTES);
    gru_persistent<<<NBLK, NTHR, SMEM_BYTES>>>(
        (const float*)d_in[0], (const float*)d_in[1], (const float*)d_in[2],
        (const float*)d_in[3], (const float*)d_in[4], (const float*)d_in[5],
        (const float*)d_in[6], (const float*)d_in[7], (const float*)d_in[8],
        (const float*)d_in[9], (float*)d_out);
}

// round 3
// speedup vs baseline: 1.6118x; 1.6118x over previous
#include <cuda_runtime.h>

#define NBLK 144
#define NTHR 512
#define N0   56
#define N1   88
#define Bz   32
#define Ssz  2048
#define Hsz  512
#define Isz  128
#define Osz  128
#define K0   640
#define K1   1024
#define P0   644
#define P1   1028

// L0 smem offsets (floats)
#define L0_WZR   0
#define L0_WG    12800
#define L0_PART  20480
#define L0_BIAS  30720
#define L0_STAGE 30784
// L1 smem offsets
#define L1_WZR   0
#define L1_WG    12288
#define L1_WY    20480
#define L1_PART  22528
#define L1_BIAS  24576
#define L1_STAGE 24640
#define SMEM_FLOATS 57536
#define SMEM_BYTES (SMEM_FLOATS * 4)

__device__ float g_h0[2][Bz * Hsz];
__device__ float g_h1[2][Bz * Hsz];
__device__ float g_z0[Bz * Hsz];
__device__ float g_rh0[Bz * Hsz];
__device__ float g_z1[Bz * Hsz];
__device__ float g_rh1[Bz * Hsz];
__device__ unsigned g_cnt;
__device__ volatile unsigned g_gen;

__device__ __forceinline__ float4 ldcg4(const float* p) {
    float4 v;
    asm volatile("ld.global.cg.v4.f32 {%0,%1,%2,%3}, [%4];"
                 : "=f"(v.x), "=f"(v.y), "=f"(v.z), "=f"(v.w) : "l"(p));
    return v;
}
__device__ __forceinline__ float ldcgf(const float* p) {
    float v;
    asm volatile("ld.global.cg.f32 %0, [%1];" : "=f"(v) : "l"(p));
    return v;
}
__device__ __forceinline__ void stcgf(float* p, float v) {
    asm volatile("st.global.cg.f32 [%0], %1;" :: "l"(p), "f"(v));
}

__device__ __forceinline__ void grid_sync() {
    __threadfence();
    __syncthreads();
    if (threadIdx.x == 0) {
        unsigned gen = g_gen;
        if (atomicAdd(&g_cnt, 1u) == (unsigned)(NBLK - 1)) {
            g_cnt = 0u;
            __threadfence();
            g_gen = gen + 1u;
        } else {
            while (g_gen == gen) { }
        }
        __threadfence();
    }
    __syncthreads();
}

__device__ __forceinline__ float sigmoid_(float x) { return 1.0f / (1.0f + __expf(-x)); }
__device__ __forceinline__ float tanh_(float x)    { return 1.0f - 2.0f / (__expf(2.0f * x) + 1.0f); }

// jobs = ngroups*KS distributed over 16 warps; each job: 4 rows x (K/KS) chunk
template <int K, int KS, int PITCH>
__device__ __forceinline__ void run_dot(const float* __restrict__ Wsm,
                                        const float* __restrict__ stg,
                                        float* __restrict__ part,
                                        int ngroups, int soff) {
    const int wid = threadIdx.x >> 5, lane = threadIdx.x & 31;
    constexpr int KLEN = K / KS;
    for (int job = wid; job < ngroups * KS; job += 16) {
        int g = job / KS, kq = job - g * KS;
        const float* wb = Wsm + (g * 4) * K + kq * KLEN;
        const float* sb = stg + lane * PITCH + soff + kq * KLEN;
        float a0 = 0.f, a1 = 0.f, a2 = 0.f, a3 = 0.f;
#pragma unroll 8
        for (int k = 0; k < KLEN; k += 4) {
            float4 sv = *(const float4*)(sb + k);
            float4 w0 = *(const float4*)(wb + k);
            float4 w1 = *(const float4*)(wb + K + k);
            float4 w2 = *(const float4*)(wb + 2 * K + k);
            float4 w3 = *(const float4*)(wb + 3 * K + k);
            a0 = fmaf(w0.x, sv.x, fmaf(w0.y, sv.y, fmaf(w0.z, sv.z, fmaf(w0.w, sv.w, a0))));
            a1 = fmaf(w1.x, sv.x, fmaf(w1.y, sv.y, fmaf(w1.z, sv.z, fmaf(w1.w, sv.w, a1))));
            a2 = fmaf(w2.x, sv.x, fmaf(w2.y, sv.y, fmaf(w2.z, sv.z, fmaf(w2.w, sv.w, a2))));
            a3 = fmaf(w3.x, sv.x, fmaf(w3.y, sv.y, fmaf(w3.z, sv.z, fmaf(w3.w, sv.w, a3))));
        }
        int r0 = g * 4;
        part[((r0 + 0) * KS + kq) * 32 + lane] = a0;
        part[((r0 + 1) * KS + kq) * 32 + lane] = a1;
        part[((r0 + 2) * KS + kq) * 32 + lane] = a2;
        part[((r0 + 3) * KS + kq) * 32 + lane] = a3;
    }
}

extern "C" __global__ void __launch_bounds__(NTHR, 1)
gru_pipe(const float* __restrict__ input, const float* __restrict__ h0in,
         const float* __restrict__ Wx0, const float* __restrict__ Wh0,
         const float* __restrict__ bh0, const float* __restrict__ Wx1,
         const float* __restrict__ Wh1, const float* __restrict__ bh1,
         const float* __restrict__ Why, const float* __restrict__ bhy,
         float* __restrict__ out) {
    extern __shared__ float sm[];
    const int tid = threadIdx.x;
    const int wid = tid >> 5, lane = tid & 31;
    const bool l0 = (blockIdx.x < N0);
    const int q = l0 ? blockIdx.x : blockIdx.x - N0;
    const int nq = l0 ? N0 : N1;

    const int zr_lo = (2 * Hsz * q) / nq,       zr_hi = (2 * Hsz * (q + 1)) / nq;
    const int g_lo  = (Hsz * q) / nq,           g_hi  = (Hsz * (q + 1)) / nq;
    const int y_lo  = (Osz * q) / nq,           y_hi  = (Osz * (q + 1)) / nq;
    const int Rzr = zr_hi - zr_lo, Rg = g_hi - g_lo, Ry = l0 ? 0 : (y_hi - y_lo);
    const int NGzr = (Rzr + 3) >> 2, NGg = (Rg + 3) >> 2;

    float* part  = sm + (l0 ? L0_PART : L1_PART);
    float* bias  = sm + (l0 ? L0_BIAS : L1_BIAS);
    float* stg   = sm + (l0 ? L0_STAGE : L1_STAGE);
    float* Wzr   = sm + (l0 ? L0_WZR : L1_WZR);
    float* Wg    = sm + (l0 ? L0_WG : L1_WG);
    float* Wy    = sm + L1_WY;

    // ---- load weights ----
    if (l0) {
        for (int i = tid; i < Rzr * K0; i += NTHR) {
            int r = i / K0, k = i - r * K0, j = zr_lo + r;
            Wzr[i] = (k < Isz) ? Wx0[j * Isz + k] : Wh0[j * Hsz + k - Isz];
        }
        for (int i = tid; i < Rg * K0; i += NTHR) {
            int r = i / K0, k = i - r * K0, j = 2 * Hsz + g_lo + r;
            Wg[i] = (k < Isz) ? Wx0[j * Isz + k] : Wh0[j * Hsz + k - Isz];
        }
        for (int i = tid; i < Rzr; i += NTHR) bias[i] = bh0[zr_lo + i];
        for (int i = tid; i < Rg; i += NTHR) bias[32 + i] = bh0[2 * Hsz + g_lo + i];
    } else {
        for (int i = tid; i < Rzr * K1; i += NTHR) {
            int r = i >> 10, k = i & 1023, j = zr_lo + r;
            Wzr[i] = (k < Hsz) ? Wx1[j * Hsz + k] : Wh1[j * Hsz + k - Hsz];
        }
        for (int i = tid; i < Rg * K1; i += NTHR) {
            int r = i >> 10, k = i & 1023, j = 2 * Hsz + g_lo + r;
            Wg[i] = (k < Hsz) ? Wx1[j * Hsz + k] : Wh1[j * Hsz + k - Hsz];
        }
        for (int i = tid; i < Ry * Hsz; i += NTHR) {
            int r = i >> 9, k = i & 511;
            Wy[i] = Why[(y_lo + r) * Hsz + k];
        }
        for (int i = tid; i < Rzr; i += NTHR) bias[i] = bh1[zr_lo + i];
        for (int i = tid; i < Rg; i += NTHR) bias[32 + i] = bh1[2 * Hsz + g_lo + i];
        for (int i = tid; i < Ry; i += NTHR) bias[56 + i] = bhy[y_lo + i];
    }
    // ---- init hidden state ----
    {
        int i = blockIdx.x * NTHR + tid;
        if (i < Bz * 2 * Hsz) {
            int b = i >> 10, rest = i & 1023;
            float v = h0in[i];
            if (rest < Hsz) stcgf(&g_h0[0][b * Hsz + rest], v);
            else            stcgf(&g_h1[0][b * Hsz + rest - Hsz], v);
        }
    }
    __syncthreads();
    grid_sync();

    for (int tau = 0; tau <= Ssz; ++tau) {
        // ================= PHASE 1 =================
        if (l0) {
            if (tau < Ssz) {
                const int t = tau, par = t & 1;
                for (int i = tid; i < Bz * 32; i += NTHR) {
                    int b = i >> 5, k = (i & 31) << 2;
                    *(float4*)(stg + b * P0 + k) =
                        *(const float4*)(input + (b * Ssz + t) * Isz + k);
                }
                for (int i = tid; i < Bz * 128; i += NTHR) {
                    int b = i >> 7, k = (i & 127) << 2;
                    *(float4*)(stg + b * P0 + Isz + k) = ldcg4(&g_h0[par][b * Hsz + k]);
                }
                __syncthreads();
                run_dot<K0, 16, P0>(Wzr, stg, part, NGzr, 0);
                __syncthreads();
                for (int idx = tid; idx < Rzr * 32; idx += NTHR) {
                    int row = idx >> 5, b = idx & 31;
                    float acc = bias[row];
#pragma unroll
                    for (int kq = 0; kq < 16; ++kq) acc += part[(row * 16 + kq) * 32 + b];
                    float s = sigmoid_(acc);
                    int j = zr_lo + row;
                    if (j < Hsz) stcgf(&g_z0[b * Hsz + j], s);
                    else stcgf(&g_rh0[b * Hsz + j - Hsz], s * stg[b * P0 + Isz + (j - Hsz)]);
                }
            }
        } else {
            if (tau >= 1) {
                const int bo = tau & 1, bn = (tau + 1) & 1;  // h0' buf, h1_old buf
                for (int i = tid; i < Bz * 128; i += NTHR) {
                    int b = i >> 7, k = (i & 127) << 2;
                    *(float4*)(stg + b * P1 + k)       = ldcg4(&g_h0[bo][b * Hsz + k]);
                    *(float4*)(stg + b * P1 + Hsz + k) = ldcg4(&g_h1[bn][b * Hsz + k]);
                }
                __syncthreads();
                run_dot<K1, 4, P1>(Wzr, stg, part, NGzr, 0);
                if (wid >= 12 && Ry > 0) {  // y dot on warps 12..15
                    int jq = wid - 12;
                    const float* wb = Wy + jq * 128;
                    const float* sb = stg + lane * P1 + Hsz + jq * 128;
                    float a0 = 0.f, a1 = 0.f, a2 = 0.f, a3 = 0.f;
#pragma unroll 8
                    for (int k = 0; k < 128; k += 4) {
                        float4 sv = *(const float4*)(sb + k);
                        float4 w0 = *(const float4*)(wb + k);
                        float4 w1 = *(const float4*)(wb + 512 + k);
                        float4 w2 = *(const float4*)(wb + 1024 + k);
                        float4 w3 = *(const float4*)(wb + 1536 + k);
                        a0 = fmaf(w0.x, sv.x, fmaf(w0.y, sv.y, fmaf(w0.z, sv.z, fmaf(w0.w, sv.w, a0))));
                        a1 = fmaf(w1.x, sv.x, fmaf(w1.y, sv.y, fmaf(w1.z, sv.z, fmaf(w1.w, sv.w, a1))));
                        a2 = fmaf(w2.x, sv.x, fmaf(w2.y, sv.y, fmaf(w2.z, sv.z, fmaf(w2.w, sv.w, a2))));
                        a3 = fmaf(w3.x, sv.x, fmaf(w3.y, sv.y, fmaf(w3.z, sv.z, fmaf(w3.w, sv.w, a3))));
                    }
                    part[(48 + 0 * 4 + jq) * 32 + lane] = a0;
                    part[(48 + 1 * 4 + jq) * 32 + lane] = a1;
                    part[(48 + 2 * 4 + jq) * 32 + lane] = a2;
                    part[(48 + 3 * 4 + jq) * 32 + lane] = a3;
                }
                __syncthreads();
                for (int idx = tid; idx < Rzr * 32; idx += NTHR) {
                    int row = idx >> 5, b = idx & 31;
                    float acc = bias[row];
#pragma unroll
                    for (int kq = 0; kq < 4; ++kq) acc += part[(row * 4 + kq) * 32 + b];
                    float s = sigmoid_(acc);
                    int j = zr_lo + row;
                    if (j < Hsz) stcgf(&g_z1[b * Hsz + j], s);
                    else stcgf(&g_rh1[b * Hsz + j - Hsz], s * stg[b * P1 + Hsz + (j - Hsz)]);
                }
                if (tau >= 2) {
                    for (int idx = tid; idx < Ry * 32; idx += NTHR) {
                        int row = idx >> 5, b = idx & 31;
                        float acc = bias[56 + row];
#pragma unroll
                        for (int kq = 0; kq < 4; ++kq) acc += part[(48 + row * 4 + kq) * 32 + b];
                        out[(b * Ssz + (tau - 2)) * Osz + (y_lo + row)] = acc;
                    }
                }
            }
        }
        grid_sync();

        // ================= PHASE 2 =================
        if (l0) {
            if (tau < Ssz) {
                const int par = tau & 1, nxt = par ^ 1;
                for (int i = tid; i < Bz * 128; i += NTHR) {
                    int b = i >> 7, k = (i & 127) << 2;
                    *(float4*)(stg + b * P0 + Isz + k) = ldcg4(&g_rh0[b * Hsz + k]);
                }
                __syncthreads();
                run_dot<K0, 16, P0>(Wg, stg, part, NGg, 0);
                __syncthreads();
                for (int idx = tid; idx < Rg * 32; idx += NTHR) {
                    int row = idx >> 5, b = idx & 31;
                    float acc = bias[32 + row];
#pragma unroll
                    for (int kq = 0; kq < 16; ++kq) acc += part[(row * 16 + kq) * 32 + b];
                    float g = tanh_(acc);
                    int u = g_lo + row;
                    float z = ldcgf(&g_z0[b * Hsz + u]);
                    float h = ldcgf(&g_h0[par][b * Hsz + u]);
                    stcgf(&g_h0[nxt][b * Hsz + u], z * h + (1.f - z) * g);
                }
            }
        } else {
            if (tau >= 1) {
                const int bo = (tau + 1) & 1, bn = tau & 1;  // old, new h1 bufs
                for (int i = tid; i < Bz * 128; i += NTHR) {
                    int b = i >> 7, k = (i & 127) << 2;
                    *(float4*)(stg + b * P1 + Hsz + k) = ldcg4(&g_rh1[b * Hsz + k]);
                }
                __syncthreads();
                run_dot<K1, 8, P1>(Wg, stg, part, NGg, 0);
                __syncthreads();
                for (int idx = tid; idx < Rg * 32; idx += NTHR) {
                    int row = idx >> 5, b = idx & 31;
                    float acc = bias[32 + row];
#pragma unroll
                    for (int kq = 0; kq < 8; ++kq) acc += part[(row * 8 + kq) * 32 + b];
                    float g = tanh_(acc);
                    int u = g_lo + row;
                    float z = ldcgf(&g_z1[b * Hsz + u]);
                    float h = ldcgf(&g_h1[bo][b * Hsz + u]);
                    stcgf(&g_h1[bn][b * Hsz + u], z * h + (1.f - z) * g);
                }
            }
        }
        grid_sync();
    }

    // ===== Epilogue: y(S-1) from final h1 (buffer 0), hidden_state =====
    if (!l0 && Ry > 0) {
        for (int idx = tid; idx < Ry * 32; idx += NTHR) {
            int row = idx >> 5, b = idx & 31;
            const float* wy = Wy + row * Hsz;
            float acc = bias[56 + row];
            for (int k = 0; k < Hsz; k += 4) {
                float4 h = ldcg4(&g_h1[0][b * Hsz + k]);
                float4 w = *(const float4*)(wy + k);
                acc = fmaf(w.x, h.x, fmaf(w.y, h.y, fmaf(w.z, h.z, fmaf(w.w, h.w, acc))));
            }
            out[(b * Ssz + (Ssz - 1)) * Osz + (y_lo + row)] = acc;
        }
    }
    {
        int i = blockIdx.x * NTHR + tid;
        if (i < Bz * 2 * Hsz) {
            int b = i >> 10, rest = i & 1023;
            float v = (rest < Hsz) ? ldcgf(&g_h0[0][b * Hsz + rest])
                                   : ldcgf(&g_h1[0][b * Hsz + rest - Hsz]);
            out[Bz * Ssz * Osz + i] = v;
        }
    }
}

extern "C" void kernel_launch(void* const* d_in, const int* in_sizes, int n_in,
                              void* d_out, int out_size) {
    cudaFuncSetAttribute(gru_pipe,
                         cudaFuncAttributeMaxDynamicSharedMemorySize, SMEM_BYTES);
    gru_pipe<<<NBLK, NTHR, SMEM_BYTES>>>(
        (const float*)d_in[0], (const float*)d_in[1], (const float*)d_in[2],
        (const float*)d_in[3], (const float*)d_in[4], (const float*)d_in[5],
        (const float*)d_in[6], (const float*)d_in[7], (const float*)d_in[8],
        (const float*)d_in[9], (float*)d_out);
}

// round 4
// speedup vs baseline: 1.6938x; 1.0508x over previous
#include <cuda_runtime.h>

#define NBLK 144
#define N0   54
#define N1   90
#define NTHR 512
#define Bz   32
#define Ssz  2048
#define Isz  128
#define Hsz  512
#define Osz  128
#define K0   640
#define K1   1024
#define P0   644
#define PH   516

// smem float offsets
#define OFF_BIAS  0
#define OFF_PARTZ 64
#define OFF_PARTG 6208
#define OFF_PARTY 12352
#define OFF_STAGE 13376
#define OFF_W     34048
#define OFF_WY    54528
#define SMEM_FLOATS 56640
#define SMEM_BYTES (SMEM_FLOATS * 4)
#define BZ 0
#define BG 24
#define BY 40

__device__ float g_h0[2][Bz * Hsz];
__device__ float g_h1[2][Bz * Hsz];
__device__ float g_z0[Bz * Hsz];
__device__ float g_rh0[Bz * Hsz];
__device__ float g_z1[Bz * Hsz];
__device__ float g_rh1[Bz * Hsz];
__device__ unsigned g_count;

__device__ __forceinline__ float4 ldcg4(const float* p) {
    float4 v;
    asm volatile("ld.global.cg.v4.f32 {%0,%1,%2,%3}, [%4];"
                 : "=f"(v.x), "=f"(v.y), "=f"(v.z), "=f"(v.w) : "l"(p));
    return v;
}
__device__ __forceinline__ float ldcgf(const float* p) {
    float v;
    asm volatile("ld.global.cg.f32 %0, [%1];" : "=f"(v) : "l"(p));
    return v;
}
__device__ __forceinline__ void stcgf(float* p, float v) {
    asm volatile("st.global.cg.f32 [%0], %1;" :: "l"(p), "f"(v));
}

__device__ __forceinline__ void grid_sync(unsigned target) {
    __syncthreads();
    if (threadIdx.x == 0) {
        asm volatile("red.release.gpu.add.u32 [%0], %1;"
                     :: "l"(&g_count), "r"(1u) : "memory");
        unsigned v;
        do {
            asm volatile("ld.acquire.gpu.u32 %0, [%1];"
                         : "=r"(v) : "l"(&g_count) : "memory");
        } while (v < target);
    }
    __syncthreads();
}

__device__ __forceinline__ float sigmoid_(float x) { return 1.0f / (1.0f + __expf(-x)); }
__device__ __forceinline__ float tanh_(float x)    { return 1.0f - 2.0f / (__expf(2.0f * x) + 1.0f); }

// packed fp32x2 fma: d = w*s + acc
__device__ __forceinline__ unsigned long long f2(unsigned long long w,
                                                 unsigned long long s,
                                                 unsigned long long acc) {
    unsigned long long d;
    asm("fma.rn.f32x2 %0, %1, %2, %3;" : "=l"(d) : "l"(w), "l"(s), "l"(acc));
    return d;
}

template <int KLEN, int ROWS>
__device__ __forceinline__ void dot_job(const float* __restrict__ wb, int wstride,
                                        const float* __restrict__ sb,
                                        float* __restrict__ pd, int prs) {
    unsigned long long acc[2 * ROWS];
#pragma unroll
    for (int i = 0; i < 2 * ROWS; ++i) acc[i] = 0ull;
#pragma unroll 2
    for (int k = 0; k < KLEN; k += 4) {
        ulonglong2 sv = *(const ulonglong2*)(sb + k);
#pragma unroll
        for (int r = 0; r < ROWS; ++r) {
            ulonglong2 wv = *(const ulonglong2*)(wb + r * wstride + k);
            acc[2 * r]     = f2(wv.x, sv.x, acc[2 * r]);
            acc[2 * r + 1] = f2(wv.y, sv.y, acc[2 * r + 1]);
        }
    }
#pragma unroll
    for (int r = 0; r < ROWS; ++r) {
        float2 a = *(float2*)&acc[2 * r];
        float2 b = *(float2*)&acc[2 * r + 1];
        pd[r * prs] = (a.x + a.y) + (b.x + b.y);
    }
}

// jobs: NG8 groups of 8 rows + optional 4-row tail, K split KS ways (chunk KLEN)
template <int KS, int KLEN, int KSLOTS>
__device__ __forceinline__ void run_jobs(const float* __restrict__ W, int wstride,
                                         int coloff, int NG8, int tail,
                                         const float* __restrict__ stg, int pitch,
                                         float* __restrict__ part, int kqoff) {
    const int lane = threadIdx.x & 31, wid = threadIdx.x >> 5;
    const int njobs = (NG8 + tail) * KS;
    for (int job = wid; job < njobs; job += 16) {
        const int g = job / KS, kq = job - g * KS;
        const float* wb = W + (g * 8) * wstride + coloff + kq * KLEN;
        const float* sb = stg + lane * pitch + kq * KLEN;
        float* pd = part + ((g * 8) * KSLOTS + kqoff + kq) * 32 + lane;
        if (g < NG8) dot_job<KLEN, 8>(wb, wstride, sb, pd, KSLOTS * 32);
        else         dot_job<KLEN, 4>(wb, wstride, sb, pd, KSLOTS * 32);
    }
}

__global__ void reset_k() { g_count = 0u; }

extern "C" __global__ void __launch_bounds__(NTHR, 1)
gru_pipe2(const float* __restrict__ input, const float* __restrict__ h0in,
          const float* __restrict__ Wx0, const float* __restrict__ Wh0,
          const float* __restrict__ bh0, const float* __restrict__ Wx1,
          const float* __restrict__ Wh1, const float* __restrict__ bh1,
          const float* __restrict__ Why, const float* __restrict__ bhy,
          float* __restrict__ out) {
    extern __shared__ float sm[];
    const int tid = threadIdx.x;
    const bool l0 = (blockIdx.x < N0);
    const int q = l0 ? blockIdx.x : blockIdx.x - N0;

    int zr_lo, Rzr, gr_lo, Rg, y_lo = 0, Ry = 0;
    if (l0) {
        zr_lo = 4 * ((256 * q) / N0); Rzr = 4 * ((256 * (q + 1)) / N0) - zr_lo;
        gr_lo = 4 * ((128 * q) / N0); Rg  = 4 * ((128 * (q + 1)) / N0) - gr_lo;
    } else {
        zr_lo = 4 * ((256 * q) / N1); Rzr = 4 * ((256 * (q + 1)) / N1) - zr_lo;
        gr_lo = 4 * ((128 * q) / N1); Rg  = 4 * ((128 * (q + 1)) / N1) - gr_lo;
        y_lo = (Osz * q) / N1;        Ry  = (Osz * (q + 1)) / N1 - y_lo;
    }
    const int zNG8 = Rzr >> 3, zT = (Rzr & 7) ? 1 : 0;
    const int gNG8 = Rg >> 3,  gT = (Rg & 7) ? 1 : 0;

    float* bias  = sm + OFF_BIAS;
    float* partZ = sm + OFF_PARTZ;
    float* partG = sm + OFF_PARTG;
    float* partY = sm + OFF_PARTY;
    float* stg   = sm + OFF_STAGE;
    float* Wzr   = sm + OFF_W;
    float* Wg    = sm + OFF_W + (l0 ? 12800 : 12288);
    float* Wy    = sm + OFF_WY;

    // ---- weight loads (once) ----
    if (l0) {
        for (int i = tid; i < Rzr * K0; i += NTHR) {
            int r = i / K0, k = i - r * K0, j = zr_lo + r;
            Wzr[i] = (k < Isz) ? Wx0[j * Isz + k] : Wh0[j * Hsz + k - Isz];
        }
        for (int i = tid; i < Rg * K0; i += NTHR) {
            int r = i / K0, k = i - r * K0, j = 2 * Hsz + gr_lo + r;
            Wg[i] = (k < Isz) ? Wx0[j * Isz + k] : Wh0[j * Hsz + k - Isz];
        }
        if (tid < Rzr) bias[BZ + tid] = bh0[zr_lo + tid];
        if (tid >= 32 && tid - 32 < Rg) bias[BG + tid - 32] = bh0[2 * Hsz + gr_lo + tid - 32];
    } else {
        for (int i = tid; i < Rzr * K1; i += NTHR) {
            int r = i >> 10, k = i & 1023, j = zr_lo + r;
            Wzr[i] = (k < Hsz) ? Wx1[j * Hsz + k] : Wh1[j * Hsz + k - Hsz];
        }
        for (int i = tid; i < Rg * K1; i += NTHR) {
            int r = i >> 10, k = i & 1023, j = 2 * Hsz + gr_lo + r;
            Wg[i] = (k < Hsz) ? Wx1[j * Hsz + k] : Wh1[j * Hsz + k - Hsz];
        }
        for (int i = tid; i < 4 * Hsz; i += NTHR) {
            int r = i >> 9, k = i & 511;
            Wy[i] = (r < Ry) ? Why[(y_lo + r) * Hsz + k] : 0.f;
        }
        if (tid < Rzr) bias[BZ + tid] = bh1[zr_lo + tid];
        if (tid >= 32 && tid - 32 < Rg) bias[BG + tid - 32] = bh1[2 * Hsz + gr_lo + tid - 32];
        if (tid >= 64 && tid - 64 < Ry) bias[BY + tid - 64] = bhy[y_lo + tid - 64];
    }
    // ---- init hidden state (buffer 0) ----
    {
        int i = blockIdx.x * NTHR + tid;
        if (i < Bz * 2 * Hsz) {
            int b = i >> 10, rest = i & 1023;
            float v = h0in[i];
            if (rest < Hsz) stcgf(&g_h0[0][b * Hsz + rest], v);
            else            stcgf(&g_h1[0][b * Hsz + rest - Hsz], v);
        }
    }
    unsigned bar = 0;
    grid_sync(++bar * NBLK);

    for (int tau = 0; tau <= Ssz; ++tau) {
        // ================= PHASE 1 =================
        if (l0) {
            if (tau < Ssz) {
                const int par = tau & 1;
                for (int i = tid; i < Bz * 32; i += NTHR) {
                    int b = i >> 5, k = (i & 31) << 2;
                    *(float4*)(stg + b * P0 + k) =
                        *(const float4*)(input + (b * Ssz + tau) * Isz + k);
                }
                for (int i = tid; i < Bz * 128; i += NTHR) {
                    int b = i >> 7, k = (i & 127) << 2;
                    *(float4*)(stg + b * P0 + Isz + k) = ldcg4(&g_h0[par][b * Hsz + k]);
                }
                __syncthreads();
                run_jobs<8, 80, 8>(Wzr, K0, 0, zNG8, zT, stg, P0, partZ, 0);
                __syncthreads();
                for (int idx = tid; idx < Rzr * 32; idx += NTHR) {
                    int row = idx >> 5, b = idx & 31;
                    float acc = bias[BZ + row];
#pragma unroll
                    for (int kq = 0; kq < 8; ++kq) acc += partZ[(row * 8 + kq) * 32 + b];
                    float s = sigmoid_(acc);
                    int j = zr_lo + row;
                    if (j < Hsz) stcgf(&g_z0[b * Hsz + j], s);
                    else stcgf(&g_rh0[b * Hsz + j - Hsz], s * stg[b * P0 + Isz + (j - Hsz)]);
                }
            }
        } else {
            if (tau >= 1) {
                const int bo = tau & 1, bn = (tau + 1) & 1;
                // half A: h0' (x-side of zr AND of g)
                for (int i = tid; i < Bz * 128; i += NTHR) {
                    int b = i >> 7, k = (i & 127) << 2;
                    *(float4*)(stg + b * PH + k) = ldcg4(&g_h0[bo][b * Hsz + k]);
                }
                __syncthreads();
                run_jobs<8, 64, 16>(Wzr, K1, 0, zNG8, zT, stg, PH, partZ, 0);
                run_jobs<8, 64, 16>(Wg,  K1, 0, gNG8, gT, stg, PH, partG, 0);
                __syncthreads();
                // half B: h1_old (h-side of zr, y)
                for (int i = tid; i < Bz * 128; i += NTHR) {
                    int b = i >> 7, k = (i & 127) << 2;
                    *(float4*)(stg + b * PH + k) = ldcg4(&g_h1[bn][b * Hsz + k]);
                }
                __syncthreads();
                run_jobs<8, 64, 16>(Wzr, K1, 512, zNG8, zT, stg, PH, partZ, 8);
                run_jobs<8, 64, 8>(Wy, 512, 0, 0, 1, stg, PH, partY, 0);
                __syncthreads();
                for (int idx = tid; idx < Rzr * 32; idx += NTHR) {
                    int row = idx >> 5, b = idx & 31;
                    float acc = bias[BZ + row];
#pragma unroll
                    for (int kq = 0; kq < 16; ++kq) acc += partZ[(row * 16 + kq) * 32 + b];
                    float s = sigmoid_(acc);
                    int j = zr_lo + row;
                    if (j < Hsz) stcgf(&g_z1[b * Hsz + j], s);
                    else stcgf(&g_rh1[b * Hsz + j - Hsz], s * stg[b * PH + (j - Hsz)]);
                }
                if (tau >= 2) {
                    for (int idx = tid; idx < Ry * 32; idx += NTHR) {
                        int row = idx >> 5, b = idx & 31;
                        float acc = bias[BY + row];
#pragma unroll
                        for (int kq = 0; kq < 8; ++kq) acc += partY[(row * 8 + kq) * 32 + b];
                        out[(b * Ssz + (tau - 2)) * Osz + y_lo + row] = acc;
                    }
                }
            }
        }
        grid_sync(++bar * NBLK);

        // ================= PHASE 2 =================
        if (l0) {
            if (tau < Ssz) {
                const int par = tau & 1, nxt = par ^ 1;
                for (int i = tid; i < Bz * 128; i += NTHR) {
                    int b = i >> 7, k = (i & 127) << 2;
                    *(float4*)(stg + b * P0 + Isz + k) = ldcg4(&g_rh0[b * Hsz + k]);
                }
                __syncthreads();
                run_jobs<16, 40, 16>(Wg, K0, 0, gNG8, gT, stg, P0, partG, 0);
                __syncthreads();
                for (int idx = tid; idx < Rg * 32; idx += NTHR) {
                    int row = idx >> 5, b = idx & 31;
                    float acc = bias[BG + row];
#pragma unroll
                    for (int kq = 0; kq < 16; ++kq) acc += partG[(row * 16 + kq) * 32 + b];
                    float g = tanh_(acc);
                    int u = gr_lo + row;
                    float z = ldcgf(&g_z0[b * Hsz + u]);
                    float h = ldcgf(&g_h0[par][b * Hsz + u]);
                    stcgf(&g_h0[nxt][b * Hsz + u], z * h + (1.f - z) * g);
                }
            }
        } else {
            if (tau >= 1) {
                const int bo = (tau + 1) & 1, bn = tau & 1;
                for (int i = tid; i < Bz * 128; i += NTHR) {
                    int b = i >> 7, k = (i & 127) << 2;
                    *(float4*)(stg + b * PH + k) = ldcg4(&g_rh1[b * Hsz + k]);
                }
                __syncthreads();
                run_jobs<8, 64, 16>(Wg, K1, 512, gNG8, gT, stg, PH, partG, 8);
                __syncthreads();
                for (int idx = tid; idx < Rg * 32; idx += NTHR) {
                    int row = idx >> 5, b = idx & 31;
                    float acc = bias[BG + row];
#pragma unroll
                    for (int kq = 0; kq < 16; ++kq) acc += partG[(row * 16 + kq) * 32 + b];
                    float g = tanh_(acc);
                    int u = gr_lo + row;
                    float z = ldcgf(&g_z1[b * Hsz + u]);
                    float h = ldcgf(&g_h1[bo][b * Hsz + u]);
                    stcgf(&g_h1[bn][b * Hsz + u], z * h + (1.f - z) * g);
                }
            }
        }
        grid_sync(++bar * NBLK);
    }

    // ===== Epilogue =====
    if (!l0 && Ry > 0) {
        for (int idx = tid; idx < Ry * 32; idx += NTHR) {
            int row = idx >> 5, b = idx & 31;
            const float* wy = Wy + row * Hsz;
            float acc = bias[BY + row];
            for (int k = 0; k < Hsz; k += 4) {
                float4 h = ldcg4(&g_h1[0][b * Hsz + k]);
                float4 w = *(const float4*)(wy + k);
                acc = fmaf(w.x, h.x, fmaf(w.y, h.y, fmaf(w.z, h.z, fmaf(w.w, h.w, acc))));
            }
            out[(b * Ssz + (Ssz - 1)) * Osz + (y_lo + row)] = acc;
        }
    }
    {
        int i = blockIdx.x * NTHR + tid;
        if (i < Bz * 2 * Hsz) {
            int b = i >> 10, rest = i & 1023;
            float v = (rest < Hsz) ? ldcgf(&g_h0[0][b * Hsz + rest])
                                   : ldcgf(&g_h1[0][b * Hsz + rest - Hsz]);
            out[Bz * Ssz * Osz + i] = v;
        }
    }
}

extern "C" void kernel_launch(void* const* d_in, const int* in_sizes, int n_in,
                              void* d_out, int out_size) {
    cudaFuncSetAttribute(gru_pipe2,
                         cudaFuncAttributeMaxDynamicSharedMemorySize, SMEM_BYTES);
    reset_k<<<1, 1>>>();
    gru_pipe2<<<NBLK, NTHR, SMEM_BYTES>>>(
        (const float*)d_in[0], (const float*)d_in[1], (const float*)d_in[2],
        (const float*)d_in[3], (const float*)d_in[4], (const float*)d_in[5],
        (const float*)d_in[6], (const float*)d_in[7], (const float*)d_in[8],
        (const float*)d_in[9], (float*)d_out);
}

// round 5
// speedup vs baseline: 1.6981x; 1.0026x over previous
#include <cuda_runtime.h>

#define NBLK 144
#define N0   54
#define N1   90
#define NTHR 512
#define Bz   32
#define Ssz  2048
#define Isz  128
#define Hsz  512
#define Osz  128
#define K0   640
#define K1   1024
#define P0   644
#define PH   516

// smem float offsets
#define OFF_BIAS  0
#define OFF_PARTZ 64
#define OFF_PARTG 6208
#define OFF_PARTY 12352
#define OFF_STAGE 13376
#define OFF_W     34048
#define OFF_WY    54528
#define SMEM_FLOATS 56640
#define SMEM_BYTES (SMEM_FLOATS * 4)
#define BZ 0
#define BG 24
#define BY 40

__device__ float g_h0[2][Bz * Hsz];
__device__ float g_h1[2][Bz * Hsz];
__device__ float g_z0[Bz * Hsz];
__device__ float g_rh0[Bz * Hsz];
__device__ float g_z1[Bz * Hsz];
__device__ float g_rh1[Bz * Hsz];
__device__ unsigned g_count;

__device__ __forceinline__ float4 ldcg4(const float* p) {
    float4 v;
    asm volatile("ld.global.cg.v4.f32 {%0,%1,%2,%3}, [%4];"
                 : "=f"(v.x), "=f"(v.y), "=f"(v.z), "=f"(v.w) : "l"(p));
    return v;
}
__device__ __forceinline__ float ldcgf(const float* p) {
    float v;
    asm volatile("ld.global.cg.f32 %0, [%1];" : "=f"(v) : "l"(p));
    return v;
}
__device__ __forceinline__ void stcgf(float* p, float v) {
    asm volatile("st.global.cg.f32 [%0], %1;" :: "l"(p), "f"(v));
}

__device__ __forceinline__ void grid_sync(unsigned target) {
    __syncthreads();
    if (threadIdx.x == 0) {
        asm volatile("red.release.gpu.add.u32 [%0], %1;"
                     :: "l"(&g_count), "r"(1u) : "memory");
        unsigned v;
        do {
            asm volatile("ld.acquire.gpu.u32 %0, [%1];"
                         : "=r"(v) : "l"(&g_count) : "memory");
        } while (v < target);
    }
    __syncthreads();
}

__device__ __forceinline__ float sigmoid_(float x) { return 1.0f / (1.0f + __expf(-x)); }
__device__ __forceinline__ float tanh_(float x)    { return 1.0f - 2.0f / (__expf(2.0f * x) + 1.0f); }

// packed fp32x2 fma: d = w*s + acc
__device__ __forceinline__ unsigned long long f2(unsigned long long w,
                                                 unsigned long long s,
                                                 unsigned long long acc) {
    unsigned long long d;
    asm("fma.rn.f32x2 %0, %1, %2, %3;" : "=l"(d) : "l"(w), "l"(s), "l"(acc));
    return d;
}

template <int KLEN, int ROWS>
__device__ __forceinline__ void dot_job(const float* __restrict__ wb, int wstride,
                                        const float* __restrict__ sb,
                                        float* __restrict__ pd, int prs) {
    unsigned long long acc[2 * ROWS];
#pragma unroll
    for (int i = 0; i < 2 * ROWS; ++i) acc[i] = 0ull;
#pragma unroll 2
    for (int k = 0; k < KLEN; k += 4) {
        ulonglong2 sv = *(const ulonglong2*)(sb + k);
#pragma unroll
        for (int r = 0; r < ROWS; ++r) {
            ulonglong2 wv = *(const ulonglong2*)(wb + r * wstride + k);
            acc[2 * r]     = f2(wv.x, sv.x, acc[2 * r]);
            acc[2 * r + 1] = f2(wv.y, sv.y, acc[2 * r + 1]);
        }
    }
#pragma unroll
    for (int r = 0; r < ROWS; ++r) {
        float2 a = *(float2*)&acc[2 * r];
        float2 b = *(float2*)&acc[2 * r + 1];
        pd[r * prs] = (a.x + a.y) + (b.x + b.y);
    }
}

// jobs: NG8 groups of 8 rows + optional 4-row tail, K split KS ways (chunk KLEN)
template <int KS, int KLEN, int KSLOTS>
__device__ __forceinline__ void run_jobs(const float* __restrict__ W, int wstride,
                                         int coloff, int NG8, int tail,
                                         const float* __restrict__ stg, int pitch,
                                         float* __restrict__ part, int kqoff) {
    const int lane = threadIdx.x & 31, wid = threadIdx.x >> 5;
    const int njobs = (NG8 + tail) * KS;
    for (int job = wid; job < njobs; job += 16) {
        const int g = job / KS, kq = job - g * KS;
        const float* wb = W + (g * 8) * wstride + coloff + kq * KLEN;
        const float* sb = stg + lane * pitch + kq * KLEN;
        float* pd = part + ((g * 8) * KSLOTS + kqoff + kq) * 32 + lane;
        if (g < NG8) dot_job<KLEN, 8>(wb, wstride, sb, pd, KSLOTS * 32);
        else         dot_job<KLEN, 4>(wb, wstride, sb, pd, KSLOTS * 32);
    }
}

__global__ void reset_k() { g_count = 0u; }

extern "C" __global__ void __launch_bounds__(NTHR, 1)
gru_pipe2(const float* __restrict__ input, const float* __restrict__ h0in,
          const float* __restrict__ Wx0, const float* __restrict__ Wh0,
          const float* __restrict__ bh0, const float* __restrict__ Wx1,
          const float* __restrict__ Wh1, const float* __restrict__ bh1,
          const float* __restrict__ Why, const float* __restrict__ bhy,
          float* __restrict__ out) {
    extern __shared__ float sm[];
    const int tid = threadIdx.x;
    const bool l0 = (blockIdx.x < N0);
    const int q = l0 ? blockIdx.x : blockIdx.x - N0;

    int zr_lo, Rzr, gr_lo, Rg, y_lo = 0, Ry = 0;
    if (l0) {
        zr_lo = 4 * ((256 * q) / N0); Rzr = 4 * ((256 * (q + 1)) / N0) - zr_lo;
        gr_lo = 4 * ((128 * q) / N0); Rg  = 4 * ((128 * (q + 1)) / N0) - gr_lo;
    } else {
        zr_lo = 4 * ((256 * q) / N1); Rzr = 4 * ((256 * (q + 1)) / N1) - zr_lo;
        gr_lo = 4 * ((128 * q) / N1); Rg  = 4 * ((128 * (q + 1)) / N1) - gr_lo;
        y_lo = (Osz * q) / N1;        Ry  = (Osz * (q + 1)) / N1 - y_lo;
    }
    const int zNG8 = Rzr >> 3, zT = (Rzr & 7) ? 1 : 0;
    const int gNG8 = Rg >> 3,  gT = (Rg & 7) ? 1 : 0;

    float* bias  = sm + OFF_BIAS;
    float* partZ = sm + OFF_PARTZ;
    float* partG = sm + OFF_PARTG;
    float* partY = sm + OFF_PARTY;
    float* stg   = sm + OFF_STAGE;
    float* Wzr   = sm + OFF_W;
    float* Wg    = sm + OFF_W + (l0 ? 12800 : 12288);
    float* Wy    = sm + OFF_WY;

    // ---- weight loads (once) ----
    if (l0) {
        for (int i = tid; i < Rzr * K0; i += NTHR) {
            int r = i / K0, k = i - r * K0, j = zr_lo + r;
            Wzr[i] = (k < Isz) ? Wx0[j * Isz + k] : Wh0[j * Hsz + k - Isz];
        }
        for (int i = tid; i < Rg * K0; i += NTHR) {
            int r = i / K0, k = i - r * K0, j = 2 * Hsz + gr_lo + r;
            Wg[i] = (k < Isz) ? Wx0[j * Isz + k] : Wh0[j * Hsz + k - Isz];
        }
        if (tid < Rzr) bias[BZ + tid] = bh0[zr_lo + tid];
        if (tid >= 32 && tid - 32 < Rg) bias[BG + tid - 32] = bh0[2 * Hsz + gr_lo + tid - 32];
    } else {
        for (int i = tid; i < Rzr * K1; i += NTHR) {
            int r = i >> 10, k = i & 1023, j = zr_lo + r;
            Wzr[i] = (k < Hsz) ? Wx1[j * Hsz + k] : Wh1[j * Hsz + k - Hsz];
        }
        for (int i = tid; i < Rg * K1; i += NTHR) {
            int r = i >> 10, k = i & 1023, j = 2 * Hsz + gr_lo + r;
            Wg[i] = (k < Hsz) ? Wx1[j * Hsz + k] : Wh1[j * Hsz + k - Hsz];
        }
        for (int i = tid; i < 4 * Hsz; i += NTHR) {
            int r = i >> 9, k = i & 511;
            Wy[i] = (r < Ry) ? Why[(y_lo + r) * Hsz + k] : 0.f;
        }
        if (tid < Rzr) bias[BZ + tid] = bh1[zr_lo + tid];
        if (tid >= 32 && tid - 32 < Rg) bias[BG + tid - 32] = bh1[2 * Hsz + gr_lo + tid - 32];
        if (tid >= 64 && tid - 64 < Ry) bias[BY + tid - 64] = bhy[y_lo + tid - 64];
    }
    // ---- init hidden state (buffer 0) ----
    {
        int i = blockIdx.x * NTHR + tid;
        if (i < Bz * 2 * Hsz) {
            int b = i >> 10, rest = i & 1023;
            float v = h0in[i];
            if (rest < Hsz) stcgf(&g_h0[0][b * Hsz + rest], v);
            else            stcgf(&g_h1[0][b * Hsz + rest - Hsz], v);
        }
    }
    unsigned bar = 0;
    grid_sync(++bar * NBLK);

    for (int tau = 0; tau <= Ssz; ++tau) {
        // ================= PHASE 1 =================
        if (l0) {
            if (tau < Ssz) {
                const int par = tau & 1;
                for (int i = tid; i < Bz * 32; i += NTHR) {
                    int b = i >> 5, k = (i & 31) << 2;
                    *(float4*)(stg + b * P0 + k) =
                        *(const float4*)(input + (b * Ssz + tau) * Isz + k);
                }
                for (int i = tid; i < Bz * 128; i += NTHR) {
                    int b = i >> 7, k = (i & 127) << 2;
                    *(float4*)(stg + b * P0 + Isz + k) = ldcg4(&g_h0[par][b * Hsz + k]);
                }
                __syncthreads();
                run_jobs<8, 80, 8>(Wzr, K0, 0, zNG8, zT, stg, P0, partZ, 0);
                __syncthreads();
                for (int idx = tid; idx < Rzr * 32; idx += NTHR) {
                    int row = idx >> 5, b = idx & 31;
                    float acc = bias[BZ + row];
#pragma unroll
                    for (int kq = 0; kq < 8; ++kq) acc += partZ[(row * 8 + kq) * 32 + b];
                    float s = sigmoid_(acc);
                    int j = zr_lo + row;
                    if (j < Hsz) stcgf(&g_z0[b * Hsz + j], s);
                    else stcgf(&g_rh0[b * Hsz + j - Hsz], s * stg[b * P0 + Isz + (j - Hsz)]);
                }
            }
        } else {
            if (tau >= 1) {
                const int bo = tau & 1, bn = (tau + 1) & 1;
                // half A: h0' (x-side of zr AND of g)
                for (int i = tid; i < Bz * 128; i += NTHR) {
                    int b = i >> 7, k = (i & 127) << 2;
                    *(float4*)(stg + b * PH + k) = ldcg4(&g_h0[bo][b * Hsz + k]);
                }
                __syncthreads();
                run_jobs<8, 64, 16>(Wzr, K1, 0, zNG8, zT, stg, PH, partZ, 0);
                run_jobs<8, 64, 16>(Wg,  K1, 0, gNG8, gT, stg, PH, partG, 0);
                __syncthreads();
                // half B: h1_old (h-side of zr, y)
                for (int i = tid; i < Bz * 128; i += NTHR) {
                    int b = i >> 7, k = (i & 127) << 2;
                    *(float4*)(stg + b * PH + k) = ldcg4(&g_h1[bn][b * Hsz + k]);
                }
                __syncthreads();
                run_jobs<8, 64, 16>(Wzr, K1, 512, zNG8, zT, stg, PH, partZ, 8);
                run_jobs<8, 64, 8>(Wy, 512, 0, 0, 1, stg, PH, partY, 0);
                __syncthreads();
                for (int idx = tid; idx < Rzr * 32; idx += NTHR) {
                    int row = idx >> 5, b = idx & 31;
                    float acc = bias[BZ + row];
#pragma unroll
                    for (int kq = 0; kq < 16; ++kq) acc += partZ[(row * 16 + kq) * 32 + b];
                    float s = sigmoid_(acc);
                    int j = zr_lo + row;
                    if (j < Hsz) stcgf(&g_z1[b * Hsz + j], s);
                    else stcgf(&g_rh1[b * Hsz + j - Hsz], s * stg[b * PH + (j - Hsz)]);
                }
                if (tau >= 2) {
                    for (int idx = tid; idx < Ry * 32; idx += NTHR) {
                        int row = idx >> 5, b = idx & 31;
                        float acc = bias[BY + row];
#pragma unroll
                        for (int kq = 0; kq < 8; ++kq) acc += partY[(row * 8 + kq) * 32 + b];
                        out[(b * Ssz + (tau - 2)) * Osz + y_lo + row] = acc;
                    }
                }
            }
        }
        grid_sync(++bar * NBLK);

        // ================= PHASE 2 =================
        if (l0) {
            if (tau < Ssz) {
                const int par = tau & 1, nxt = par ^ 1;
                for (int i = tid; i < Bz * 128; i += NTHR) {
                    int b = i >> 7, k = (i & 127) << 2;
                    *(float4*)(stg + b * P0 + Isz + k) = ldcg4(&g_rh0[b * Hsz + k]);
                }
                __syncthreads();
                run_jobs<16, 40, 16>(Wg, K0, 0, gNG8, gT, stg, P0, partG, 0);
                __syncthreads();
                for (int idx = tid; idx < Rg * 32; idx += NTHR) {
                    int row = idx >> 5, b = idx & 31;
                    float acc = bias[BG + row];
#pragma unroll
                    for (int kq = 0; kq < 16; ++kq) acc += partG[(row * 16 + kq) * 32 + b];
                    float g = tanh_(acc);
                    int u = gr_lo + row;
                    float z = ldcgf(&g_z0[b * Hsz + u]);
                    float h = ldcgf(&g_h0[par][b * Hsz + u]);
                    stcgf(&g_h0[nxt][b * Hsz + u], z * h + (1.f - z) * g);
                }
            }
        } else {
            if (tau >= 1) {
                const int bo = (tau + 1) & 1, bn = tau & 1;
                for (int i = tid; i < Bz * 128; i += NTHR) {
                    int b = i >> 7, k = (i & 127) << 2;
                    *(float4*)(stg + b * PH + k) = ldcg4(&g_rh1[b * Hsz + k]);
                }
                __syncthreads();
                run_jobs<8, 64, 16>(Wg, K1, 512, gNG8, gT, stg, PH, partG, 8);
                __syncthreads();
                for (int idx = tid; idx < Rg * 32; idx += NTHR) {
                    int row = idx >> 5, b = idx & 31;
                    float acc = bias[BG + row];
#pragma unroll
                    for (int kq = 0; kq < 16; ++kq) acc += partG[(row * 16 + kq) * 32 + b];
                    float g = tanh_(acc);
                    int u = gr_lo + row;
                    float z = ldcgf(&g_z1[b * Hsz + u]);
                    float h = ldcgf(&g_h1[bo][b * Hsz + u]);
                    stcgf(&g_h1[bn][b * Hsz + u], z * h + (1.f - z) * g);
                }
            }
        }
        grid_sync(++bar * NBLK);
    }

    // ===== Epilogue =====
    if (!l0 && Ry > 0) {
        for (int idx = tid; idx < Ry * 32; idx += NTHR) {
            int row = idx >> 5, b = idx & 31;
            const float* wy = Wy + row * Hsz;
            float acc = bias[BY + row];
            for (int k = 0; k < Hsz; k += 4) {
                float4 h = ldcg4(&g_h1[0][b * Hsz + k]);
                float4 w = *(const float4*)(wy + k);
                acc = fmaf(w.x, h.x, fmaf(w.y, h.y, fmaf(w.z, h.z, fmaf(w.w, h.w, acc))));
            }
            out[(b * Ssz + (Ssz - 1)) * Osz + (y_lo + row)] = acc;
        }
    }
    {
        int i = blockIdx.x * NTHR + tid;
        if (i < Bz * 2 * Hsz) {
            int b = i >> 10, rest = i & 1023;
            float v = (rest < Hsz) ? ldcgf(&g_h0[0][b * Hsz + rest])
                                   : ldcgf(&g_h1[0][b * Hsz + rest - Hsz]);
            out[Bz * Ssz * Osz + i] = v;
        }
    }
}

extern "C" void kernel_launch(void* const* d_in, const int* in_sizes, int n_in,
                              void* d_out, int out_size) {
    cudaFuncSetAttribute(gru_pipe2,
                         cudaFuncAttributeMaxDynamicSharedMemorySize, SMEM_BYTES);
    reset_k<<<1, 1>>>();
    gru_pipe2<<<NBLK, NTHR, SMEM_BYTES>>>(
        (const float*)d_in[0], (const float*)d_in[1], (const float*)d_in[2],
        (const float*)d_in[3], (const float*)d_in[4], (const float*)d_in[5],
        (const float*)d_in[6], (const float*)d_in[7], (const float*)d_in[8],
        (const float*)d_in[9], (float*)d_out);
}